// round 13
// baseline (speedup 1.0000x reference)
#include <cuda_runtime.h>
#include <cuda_bf16.h>
#include <cstdint>
#include <math.h>

#define DINL __device__ __forceinline__
DINL float sigm(float x) { return 1.0f / (1.0f + expf(-x)); }          // accurate (encoders)
DINL float fsigm(float x) { return __fdividef(1.0f, 1.0f + __expf(-x)); } // fast (decoder)
DINL float ftanh(float x) { float y; asm("tanh.approx.f32 %0, %1;" : "=f"(y) : "f"(x)); return y; }

DINL uint32_t mapa_u32(uint32_t addr, int rank) {
    uint32_t r;
    asm("mapa.shared::cluster.u32 %0, %1, %2;" : "=r"(r) : "r"(addr), "r"(rank));
    return r;
}
DINL void st_remote_f32(uint32_t raddr, float v) {
    asm volatile("st.shared::cluster.f32 [%0], %1;" :: "r"(raddr), "f"(v) : "memory");
}
DINL void mbar_init(uint32_t addr, uint32_t cnt) {
    asm volatile("mbarrier.init.shared.b64 [%0], %1;" :: "r"(addr), "r"(cnt) : "memory");
}
DINL void mbar_arrive_remote(uint32_t raddr) {
    asm volatile("mbarrier.arrive.release.cluster.shared::cluster.b64 _, [%0];"
                 :: "r"(raddr) : "memory");
}
DINL void mbar_wait(uint32_t addr, uint32_t parity) {
    asm volatile(
        "{\n\t"
        ".reg .pred P;\n\t"
        "LAB_%=:\n\t"
        "mbarrier.try_wait.parity.acquire.cluster.shared::cta.b64 P, [%0], %1, 0x989680;\n\t"
        "@!P bra LAB_%=;\n\t"
        "}\n"
        :: "r"(addr), "r"(parity) : "memory");
}

// ---------------- scratch (__device__ globals, no allocation) ---------------
__device__ float g_pool1[31 * 255 * 256];
__device__ float g_pool2[14 * 126 * 256];
__device__ float g_partial[64 * 14 * 1024];
__device__ float g_xbs[14 * 1024];
__device__ float g_wpool1[127 * 256];
__device__ float g_wpool2[62 * 256];
__device__ float g_xbw[62 * 1024];
__device__ float g_sh[256], g_sc[256], g_whh[256], g_wc[256];
__device__ float g_h0[256], g_c0[256];
__device__ float g_xiR[2 * 1024];
__device__ float g_WhR[8 * 256 * 128];
__device__ unsigned int g_tokbits[1196];       // 38272 token bits
__device__ float g_hs[38272 * 256];

// ============ STFT conv1 3x3 (1->256) + relu + maxpool 2x2 ===================
__global__ void __launch_bounds__(256) k_sconv1(const float* __restrict__ in,
                                                const float* __restrict__ w,
                                                const float* __restrict__ b) {
    const int blk = blockIdx.x;
    const int tp = blk / 255, fp = blk % 255;
    __shared__ float patch[4][4];
    const int tid = threadIdx.x;
    if (tid < 16) {
        int rr = tid >> 2, cc = tid & 3;
        patch[rr][cc] = in[(2 * tp + rr) * 513 + (2 * fp + cc)];
    }
    __syncthreads();
    const int ch = tid;
    float wr[9];
#pragma unroll
    for (int t = 0; t < 9; ++t) wr[t] = w[t * 256 + ch];
    const float bb = b[ch];
    float best = -1e30f;
#pragma unroll
    for (int a = 0; a < 2; ++a)
#pragma unroll
        for (int bc = 0; bc < 2; ++bc) {
            float acc = bb;
#pragma unroll
            for (int i = 0; i < 3; ++i)
#pragma unroll
                for (int j = 0; j < 3; ++j)
                    acc = fmaf(patch[a + i][bc + j], wr[i * 3 + j], acc);
            best = fmaxf(best, fmaxf(acc, 0.0f));
        }
    g_pool1[(tp * 255 + fp) * 256 + ch] = best;
}

// ============ STFT conv2 3x3 (256->256) + relu + maxpool 2x2 =================
__global__ void __launch_bounds__(256) k_sconv2(const float* __restrict__ w2,
                                                const float* __restrict__ b2) {
    __shared__ float sin_[4 * 8 * 256];
    const int tp = blockIdx.y;
    const int fp0 = blockIdx.x * 3;
    const int tid = threadIdx.x;
    for (int idx = tid; idx < 4 * 8 * 256; idx += 256) {
        int ch = idx & 255;
        int col = (idx >> 8) & 7;
        int row = idx >> 11;
        sin_[idx] = g_pool1[((2 * tp + row) * 255 + (2 * fp0 + col)) * 256 + ch];
    }
    __syncthreads();
    const int ch = tid;
    float a[2][6];
    const float bb = b2[ch];
#pragma unroll
    for (int r2 = 0; r2 < 2; ++r2)
#pragma unroll
        for (int cc = 0; cc < 6; ++cc) a[r2][cc] = bb;
    for (int ic = 0; ic < 256; ++ic) {
        float rv[4][8];
#pragma unroll
        for (int rr = 0; rr < 4; ++rr)
#pragma unroll
            for (int cc = 0; cc < 8; ++cc) rv[rr][cc] = sin_[(rr * 8 + cc) * 256 + ic];
#pragma unroll
        for (int i = 0; i < 3; ++i)
#pragma unroll
            for (int j = 0; j < 3; ++j) {
                float wv = w2[((i * 3 + j) * 256 + ic) * 256 + ch];
#pragma unroll
                for (int r2 = 0; r2 < 2; ++r2)
#pragma unroll
                    for (int cc = 0; cc < 6; ++cc)
                        a[r2][cc] = fmaf(wv, rv[r2 + i][cc + j], a[r2][cc]);
            }
    }
#pragma unroll
    for (int cc2 = 0; cc2 < 3; ++cc2) {
        float m = -1e30f;
#pragma unroll
        for (int r2 = 0; r2 < 2; ++r2)
#pragma unroll
            for (int q = 0; q < 2; ++q)
                m = fmaxf(m, fmaxf(a[r2][2 * cc2 + q], 0.0f));
        g_pool2[(tp * 126 + (fp0 + cc2)) * 256 + ch] = m;
    }
}

// ============ wave conv1 k3 (1024->256) + relu + pool2 =======================
__global__ void __launch_bounds__(256) k_wconv1(const float* __restrict__ in,
                                                const float* __restrict__ w,
                                                const float* __restrict__ b) {
    __shared__ float sw[4][1024];
    const int tp = blockIdx.x;
    const int tid = threadIdx.x;
    for (int idx = tid; idx < 4096; idx += 256) {
        int r = idx >> 10, k = idx & 1023;
        sw[r][k] = in[(2 * tp + r) * 1024 + k];
    }
    __syncthreads();
    const int ch = tid;
    float a0 = b[ch], a1 = b[ch];
    for (int dt = 0; dt < 3; ++dt)
        for (int k = 0; k < 1024; ++k) {
            float wv = w[(dt * 1024 + k) * 256 + ch];
            a0 = fmaf(wv, sw[dt][k], a0);
            a1 = fmaf(wv, sw[dt + 1][k], a1);
        }
    g_wpool1[tp * 256 + ch] = fmaxf(fmaxf(a0, 0.0f), fmaxf(a1, 0.0f));
}

// ============ wave conv2 k3 (256->256) + relu + pool2 ========================
__global__ void __launch_bounds__(256) k_wconv2(const float* __restrict__ w,
                                                const float* __restrict__ b) {
    __shared__ float sw[4][256];
    const int tp = blockIdx.x;
    const int tid = threadIdx.x;
    for (int idx = tid; idx < 1024; idx += 256) {
        int r = idx >> 8, k = idx & 255;
        sw[r][k] = g_wpool1[(2 * tp + r) * 256 + k];
    }
    __syncthreads();
    const int ch = tid;
    float a0 = b[ch], a1 = b[ch];
    for (int dt = 0; dt < 3; ++dt)
        for (int k = 0; k < 256; ++k) {
            float wv = w[(dt * 256 + k) * 256 + ch];
            a0 = fmaf(wv, sw[dt][k], a0);
            a1 = fmaf(wv, sw[dt + 1][k], a1);
        }
    g_wpool2[tp * 256 + ch] = fmaxf(fmaxf(a0, 0.0f), fmaxf(a1, 0.0f));
}

// ============ Xs[14,32256] @ s_Wi[32256,1024]: k-split partials ==============
__global__ void __launch_bounds__(256) k_sproj(const float* __restrict__ sWi) {
    __shared__ float xs[14 * 504];
    const int j = blockIdx.x * 256 + threadIdx.x;
    const int k0 = blockIdx.y * 504;
    for (int idx = threadIdx.x; idx < 14 * 504; idx += 256) {
        int t = idx / 504, kk = idx % 504;
        xs[idx] = g_pool2[t * 32256 + k0 + kk];
    }
    __syncthreads();
    float acc[14];
#pragma unroll
    for (int t = 0; t < 14; ++t) acc[t] = 0.f;
    for (int kk = 0; kk < 504; ++kk) {
        float wv = sWi[(size_t)(k0 + kk) * 1024 + j];
#pragma unroll
        for (int t = 0; t < 14; ++t) acc[t] = fmaf(xs[t * 504 + kk], wv, acc[t]);
    }
    for (int t = 0; t < 14; ++t)
        g_partial[(blockIdx.y * 14 + t) * 1024 + j] = acc[t];
}

__global__ void __launch_bounds__(256) k_sreduce(const float* __restrict__ sb) {
    const int idx = blockIdx.x * 256 + threadIdx.x;
    const int t = idx >> 10, j = idx & 1023;
    float a = sb[j];
    for (int kc = 0; kc < 64; ++kc) a += g_partial[(kc * 14 + t) * 1024 + j];
    g_xbs[t * 1024 + j] = a;
}

// ============ wave Wi projection =============================================
__global__ void __launch_bounds__(1024) k_wproj(const float* __restrict__ wWi,
                                                const float* __restrict__ wb) {
    __shared__ float yr[256];
    const int tid = threadIdx.x;
    if (tid < 256) yr[tid] = g_wpool2[blockIdx.x * 256 + tid];
    __syncthreads();
    float a = wb[tid];
    for (int k = 0; k < 256; ++k) a = fmaf(yr[k], wWi[k * 1024 + tid], a);
    g_xbw[blockIdx.x * 1024 + tid] = a;
}

// ============ small sequential LSTM (encoders) ===============================
__global__ void __launch_bounds__(1024) k_lstm_small(const float* __restrict__ Wh,
                                                     int mode) {
    __shared__ float h[256];
    __shared__ float zsm[1024];
    const int tid = threadIdx.x;
    const int T = mode ? 62 : 14;
    const float* xpre = mode ? g_xbw : g_xbs;
    float c = 0.0f;
    if (tid < 256) h[tid] = 0.0f;
    __syncthreads();
    for (int t = 0; t < T; ++t) {
        float acc = xpre[t * 1024 + tid];
#pragma unroll 8
        for (int k = 0; k < 256; ++k) acc = fmaf(h[k], Wh[k * 1024 + tid], acc);
        zsm[tid] = acc;
        __syncthreads();
        if (tid < 256) {
            float zi = zsm[tid], zf = zsm[256 + tid], zg = zsm[512 + tid], zo = zsm[768 + tid];
            c = sigm(zf) * c + sigm(zi) * tanhf(zg);
            h[tid] = sigm(zo) * tanhf(c);
        }
        __syncthreads();
    }
    if (tid < 256) {
        if (mode) { g_whh[tid] = h[tid]; g_wc[tid] = c; }
        else      { g_sh[tid]  = h[tid]; g_sc[tid] = c; }
    }
}

// ============ state reducers =================================================
__global__ void __launch_bounds__(256) k_reduce(const float* __restrict__ rhw,
                                                const float* __restrict__ rhb,
                                                const float* __restrict__ rcw,
                                                const float* __restrict__ rcb) {
    __shared__ float hcat[512], ccat[512];
    const int tid = threadIdx.x;
    hcat[tid] = g_sh[tid];  hcat[256 + tid] = g_whh[tid];
    ccat[tid] = g_sc[tid];  ccat[256 + tid] = g_wc[tid];
    __syncthreads();
    float ah = rhb[tid], ac = rcb[tid];
    for (int k = 0; k < 512; ++k) {
        ah = fmaf(hcat[k], rhw[k * 256 + tid], ah);
        ac = fmaf(ccat[k], rcw[k * 256 + tid], ac);
    }
    g_h0[tid] = ah;
    g_c0[tid] = ac;
}

// ============ decoder prep ===================================================
__global__ void __launch_bounds__(1024) k_dprep(const float* __restrict__ emb,
                                                const float* __restrict__ dWi,
                                                const float* __restrict__ db) {
    __shared__ float er[256];
    const int tid = threadIdx.x;
    if (tid < 256) er[tid] = emb[blockIdx.x * 256 + tid];
    __syncthreads();
    float a = db[tid];
    for (int d = 0; d < 256; ++d) a = fmaf(er[d], dWi[d * 1024 + tid], a);
    int gate = tid >> 8, cg = tid & 255, r = cg >> 5, u = cg & 31;
    g_xiR[blockIdx.x * 1024 + r * 128 + gate * 32 + u] = a;
}

__global__ void __launch_bounds__(1024) k_whprep(const float* __restrict__ dWh) {
    const int k = blockIdx.x, j = threadIdx.x;
    int gate = j >> 8, cg = j & 255, r = cg >> 5, u = cg & 31;
    g_WhR[r * 32768 + k * 128 + gate * 32 + u] = dWh[k * 1024 + j];
}

__global__ void __launch_bounds__(256) k_tokprep(const float* __restrict__ dec) {
    const int w = blockIdx.x * 256 + threadIdx.x;
    if (w >= 1196) return;
    unsigned int bits = 0;
    for (int i = 0; i < 32; ++i)
        if (dec[w * 32 + i] > 0.5f) bits |= (1u << i);
    g_tokbits[w] = bits;
}

// ============ persistent decoder: 8-CTA cluster, 38272 LSTM steps ============
// smem layout (floats): W[32768] | hb[2][256] | xis[2][128] | zs[256] |
//                       tokw[1196 u32] | pad | mbar[4 u64] @ byte 139952
__global__ void __cluster_dims__(8, 1, 1) __launch_bounds__(256, 1)
k_decoder() {
    extern __shared__ float sm[];
    float* W = sm;
    float* hb = sm + 32768;            // [2][256]
    float* xis = sm + 33280;           // [2][128]
    float* zs = sm + 33536;            // [256] (two halves summed in epilogue)
    unsigned int* tokw = (unsigned int*)(sm + 33792);
    const int r = blockIdx.x;
    const int t = threadIdx.x;
    const int jl = t & 127;
    const int half = t >> 7;

    for (int idx = t; idx < 32768; idx += 256) W[idx] = g_WhR[r * 32768 + idx];
    if (t < 128) { xis[t] = g_xiR[r * 128 + t]; xis[128 + t] = g_xiR[1024 + r * 128 + t]; }
    hb[t] = g_h0[t & 255];             // fills hb[0][0..255] (t<256)
    for (int idx = t; idx < 1196; idx += 256) tokw[idx] = g_tokbits[idx];
    float c = (t < 32) ? g_c0[r * 32 + t] : 0.0f;

    const uint32_t smem_base = (uint32_t)__cvta_generic_to_shared(sm);
    if (t == 0) {
#pragma unroll
        for (int i = 0; i < 4; ++i) mbar_init(smem_base + 139952u + 8u * i, 256);
    }
    __syncthreads();
    asm volatile("barrier.cluster.arrive.aligned;" ::: "memory");
    asm volatile("barrier.cluster.wait.aligned;" ::: "memory");

    uint32_t peer_base[8];
    if (t < 32) {
#pragma unroll
        for (int rr = 0; rr < 8; ++rr) peer_base[rr] = mapa_u32(smem_base, rr);
    }

    const float* Wc = W + half * 16384;

    for (int s = 0; s < 38272; ++s) {
        if (s) {
            mbar_wait(smem_base + 139952u + 8u * ((s - 1) & 3), ((s - 1) >> 2) & 1);
        }
        const int tok = (tokw[s >> 5] >> (s & 31)) & 1;
        const float4* h4 = (const float4*)(hb + 256 * (s & 1) + half * 128);
        float a0 = half ? 0.0f : xis[tok * 128 + jl];
        float a1 = 0.0f, a2 = 0.0f, a3 = 0.0f;
#pragma unroll 8
        for (int kk = 0; kk < 32; ++kk) {
            float4 hv = h4[kk];
            a0 = fmaf(hv.x, Wc[(4 * kk + 0) * 128 + jl], a0);
            a1 = fmaf(hv.y, Wc[(4 * kk + 1) * 128 + jl], a1);
            a2 = fmaf(hv.z, Wc[(4 * kk + 2) * 128 + jl], a2);
            a3 = fmaf(hv.w, Wc[(4 * kk + 3) * 128 + jl], a3);
        }
        zs[half * 128 + jl] = (a0 + a1) + (a2 + a3);
        __syncthreads();
        if (t < 32) {
            const int u = t;
            float zi = zs[u]      + zs[128 + u];
            float zf = zs[32 + u] + zs[160 + u];
            float zg = zs[64 + u] + zs[192 + u];
            float zo = zs[96 + u] + zs[224 + u];
            c = fsigm(zf) * c + fsigm(zi) * ftanh(zg);
            float hn = fsigm(zo) * ftanh(c);
            g_hs[(size_t)s * 256 + r * 32 + u] = hn;
            const uint32_t boff = 131072u + 1024u * ((s + 1) & 1) + (uint32_t)(r * 32 + u) * 4u;
            const uint32_t moff = 139952u + 8u * (s & 3);
#pragma unroll
            for (int rr = 0; rr < 8; ++rr) st_remote_f32(peer_base[rr] + boff, hn);
#pragma unroll
            for (int rr = 0; rr < 8; ++rr) mbar_arrive_remote(peer_base[rr] + moff);
        }
    }
}

// ============ epilogue: softmax(hs @ out_w + out_b), 16 steps/block ==========
__global__ void __launch_bounds__(128) k_softmax(const float* __restrict__ ow,
                                                 const float* __restrict__ ob,
                                                 float* __restrict__ out) {
    __shared__ float hsr[16 * 256];
    __shared__ float red[128];
    const int s0 = blockIdx.x * 16;
    const int w = threadIdx.x;
    for (int idx = w; idx < 4096; idx += 128) hsr[idx] = g_hs[(size_t)s0 * 256 + idx];
    __syncthreads();
    float a[16];
    const float bb = ob[w];
#pragma unroll
    for (int i = 0; i < 16; ++i) a[i] = bb;
    for (int d = 0; d < 256; ++d) {
        float wv = ow[d * 128 + w];
#pragma unroll
        for (int i = 0; i < 16; ++i) a[i] = fmaf(hsr[i * 256 + d], wv, a[i]);
    }
#pragma unroll 1
    for (int i = 0; i < 16; ++i) {
        red[w] = a[i];
        __syncthreads();
        for (int off = 64; off; off >>= 1) {
            if (w < off) red[w] = fmaxf(red[w], red[w + off]);
            __syncthreads();
        }
        float m = red[0];
        __syncthreads();
        float e = __expf(a[i] - m);
        red[w] = e;
        __syncthreads();
        for (int off = 64; off; off >>= 1) {
            if (w < off) red[w] += red[w + off];
            __syncthreads();
        }
        float ssum = red[0];
        __syncthreads();
        int s = s0 + i, tt = s >> 7, v = s & 127;
        out[((size_t)v * 300 + tt) * 128 + w] = e / ssum;
    }
}

// ============ zero the unwritten last time slot out[:,299,:] =================
__global__ void __launch_bounds__(256) k_zero(float* __restrict__ out) {
    const int idx = blockIdx.x * 256 + threadIdx.x;
    const int v = idx >> 7, w = idx & 127;
    out[((size_t)v * 300 + 299) * 128 + w] = 0.0f;
}

// ============================================================================
extern "C" void kernel_launch(void* const* d_in, const int* in_sizes, int n_in,
                              void* d_out, int out_size) {
    const float* stft = (const float*)d_in[0];
    const float* wave = (const float*)d_in[1];
    const float* dec  = (const float*)d_in[2];
    const float* scw1 = (const float*)d_in[3];
    const float* scb1 = (const float*)d_in[4];
    const float* scw2 = (const float*)d_in[5];
    const float* scb2 = (const float*)d_in[6];
    const float* sWi  = (const float*)d_in[7];
    const float* sWh  = (const float*)d_in[8];
    const float* sb   = (const float*)d_in[9];
    const float* wcw1 = (const float*)d_in[10];
    const float* wcb1 = (const float*)d_in[11];
    const float* wcw2 = (const float*)d_in[12];
    const float* wcb2 = (const float*)d_in[13];
    const float* wWi  = (const float*)d_in[14];
    const float* wWh  = (const float*)d_in[15];
    const float* wb   = (const float*)d_in[16];
    const float* rhw  = (const float*)d_in[17];
    const float* rhb  = (const float*)d_in[18];
    const float* rcw  = (const float*)d_in[19];
    const float* rcb  = (const float*)d_in[20];
    const float* emb  = (const float*)d_in[21];
    const float* dWi  = (const float*)d_in[22];
    const float* dWh  = (const float*)d_in[23];
    const float* db   = (const float*)d_in[24];
    const float* ow   = (const float*)d_in[25];
    const float* ob   = (const float*)d_in[26];
    float* out = (float*)d_out;
    (void)in_sizes; (void)n_in; (void)out_size;

    cudaFuncSetAttribute(k_decoder, cudaFuncAttributeMaxDynamicSharedMemorySize, 140032);

    // ---- STFT encoder ----
    k_sconv1<<<31 * 255, 256>>>(stft, scw1, scb1);
    k_sconv2<<<dim3(42, 14), 256>>>(scw2, scb2);
    k_sproj<<<dim3(4, 64), 256>>>(sWi);
    k_sreduce<<<56, 256>>>(sb);
    k_lstm_small<<<1, 1024>>>(sWh, 0);

    // ---- waveform encoder ----
    k_wconv1<<<127, 256>>>(wave, wcw1, wcb1);
    k_wconv2<<<62, 256>>>(wcw2, wcb2);
    k_wproj<<<62, 1024>>>(wWi, wb);
    k_lstm_small<<<1, 1024>>>(wWh, 1);

    // ---- reducers + decoder prep ----
    k_reduce<<<1, 256>>>(rhw, rhb, rcw, rcb);
    k_dprep<<<2, 1024>>>(emb, dWi, db);
    k_whprep<<<256, 1024>>>(dWh);
    k_tokprep<<<5, 256>>>(dec);

    // ---- sequential decoder (8-CTA cluster, persistent, mbarrier-handshake) ----
    k_decoder<<<8, 256, 140032>>>();

    // ---- parallel softmax epilogue + zero last slot ----
    k_softmax<<<2392, 128>>>(ow, ob, out);
    k_zero<<<64, 256>>>(out);
}

// round 14
// speedup vs baseline: 1.1942x; 1.1942x over previous
#include <cuda_runtime.h>
#include <cuda_bf16.h>
#include <cstdint>
#include <math.h>

#define DINL __device__ __forceinline__
DINL float sigm(float x) { return 1.0f / (1.0f + expf(-x)); }             // accurate (encoders)
DINL float fsigm(float x) { return __fdividef(1.0f, 1.0f + __expf(-x)); } // fast (decoder)
DINL float ftanh(float x) { float y; asm("tanh.approx.f32 %0, %1;" : "=f"(y) : "f"(x)); return y; }

DINL uint32_t mapa_u32(uint32_t addr, int rank) {
    uint32_t r;
    asm("mapa.shared::cluster.u32 %0, %1, %2;" : "=r"(r) : "r"(addr), "r"(rank));
    return r;
}
DINL void st_remote_f32(uint32_t raddr, float v) {
    asm volatile("st.shared::cluster.f32 [%0], %1;" :: "r"(raddr), "f"(v) : "memory");
}
DINL void mbar_init(uint32_t addr, uint32_t cnt) {
    asm volatile("mbarrier.init.shared.b64 [%0], %1;" :: "r"(addr), "r"(cnt) : "memory");
}
DINL void mbar_arrive_remote(uint32_t raddr) {
    asm volatile("mbarrier.arrive.release.cluster.shared::cluster.b64 _, [%0];"
                 :: "r"(raddr) : "memory");
}
DINL void mbar_wait(uint32_t addr, uint32_t parity) {
    asm volatile(
        "{\n\t"
        ".reg .pred P;\n\t"
        "LAB_%=:\n\t"
        "mbarrier.try_wait.parity.acquire.cluster.shared::cta.b64 P, [%0], %1, 0x989680;\n\t"
        "@!P bra LAB_%=;\n\t"
        "}\n"
        :: "r"(addr), "r"(parity) : "memory");
}

// ---------------- scratch (__device__ globals, no allocation) ---------------
__device__ float g_pool1[31 * 255 * 256];
__device__ float g_pool2[14 * 126 * 256];
__device__ float g_partial[64 * 14 * 1024];
__device__ float g_xbs[14 * 1024];
__device__ float g_wpool1[127 * 256];
__device__ float g_wpool2[62 * 256];
__device__ float g_xbw[62 * 1024];
__device__ float g_sh[256], g_sc[256], g_whh[256], g_wc[256];
__device__ float g_h0[256], g_c0[256];
__device__ float g_xiR[2 * 1024];
__device__ float g_WhR[8 * 256 * 128];
__device__ unsigned int g_tokbits[1196];
__device__ float g_hs[38272 * 256];

// ============ STFT conv1 3x3 (1->256) + relu + maxpool 2x2 ===================
__global__ void __launch_bounds__(256) k_sconv1(const float* __restrict__ in,
                                                const float* __restrict__ w,
                                                const float* __restrict__ b) {
    const int blk = blockIdx.x;
    const int tp = blk / 255, fp = blk % 255;
    __shared__ float patch[4][4];
    const int tid = threadIdx.x;
    if (tid < 16) {
        int rr = tid >> 2, cc = tid & 3;
        patch[rr][cc] = in[(2 * tp + rr) * 513 + (2 * fp + cc)];
    }
    __syncthreads();
    const int ch = tid;
    float wr[9];
#pragma unroll
    for (int t = 0; t < 9; ++t) wr[t] = w[t * 256 + ch];
    const float bb = b[ch];
    float best = -1e30f;
#pragma unroll
    for (int a = 0; a < 2; ++a)
#pragma unroll
        for (int bc = 0; bc < 2; ++bc) {
            float acc = bb;
#pragma unroll
            for (int i = 0; i < 3; ++i)
#pragma unroll
                for (int j = 0; j < 3; ++j)
                    acc = fmaf(patch[a + i][bc + j], wr[i * 3 + j], acc);
            best = fmaxf(best, fmaxf(acc, 0.0f));
        }
    g_pool1[(tp * 255 + fp) * 256 + ch] = best;
}

// ============ STFT conv2 3x3 (256->256) + relu + maxpool 2x2 =================
__global__ void __launch_bounds__(256) k_sconv2(const float* __restrict__ w2,
                                                const float* __restrict__ b2) {
    __shared__ float sin_[4 * 8 * 256];
    const int tp = blockIdx.y;
    const int fp0 = blockIdx.x * 3;
    const int tid = threadIdx.x;
    for (int idx = tid; idx < 4 * 8 * 256; idx += 256) {
        int ch = idx & 255;
        int col = (idx >> 8) & 7;
        int row = idx >> 11;
        sin_[idx] = g_pool1[((2 * tp + row) * 255 + (2 * fp0 + col)) * 256 + ch];
    }
    __syncthreads();
    const int ch = tid;
    float a[2][6];
    const float bb = b2[ch];
#pragma unroll
    for (int r2 = 0; r2 < 2; ++r2)
#pragma unroll
        for (int cc = 0; cc < 6; ++cc) a[r2][cc] = bb;
    for (int ic = 0; ic < 256; ++ic) {
        float rv[4][8];
#pragma unroll
        for (int rr = 0; rr < 4; ++rr)
#pragma unroll
            for (int cc = 0; cc < 8; ++cc) rv[rr][cc] = sin_[(rr * 8 + cc) * 256 + ic];
#pragma unroll
        for (int i = 0; i < 3; ++i)
#pragma unroll
            for (int j = 0; j < 3; ++j) {
                float wv = w2[((i * 3 + j) * 256 + ic) * 256 + ch];
#pragma unroll
                for (int r2 = 0; r2 < 2; ++r2)
#pragma unroll
                    for (int cc = 0; cc < 6; ++cc)
                        a[r2][cc] = fmaf(wv, rv[r2 + i][cc + j], a[r2][cc]);
            }
    }
#pragma unroll
    for (int cc2 = 0; cc2 < 3; ++cc2) {
        float m = -1e30f;
#pragma unroll
        for (int r2 = 0; r2 < 2; ++r2)
#pragma unroll
            for (int q = 0; q < 2; ++q)
                m = fmaxf(m, fmaxf(a[r2][2 * cc2 + q], 0.0f));
        g_pool2[(tp * 126 + (fp0 + cc2)) * 256 + ch] = m;
    }
}

// ============ wave conv1 k3 (1024->256) + relu + pool2 =======================
__global__ void __launch_bounds__(256) k_wconv1(const float* __restrict__ in,
                                                const float* __restrict__ w,
                                                const float* __restrict__ b) {
    __shared__ float sw[4][1024];
    const int tp = blockIdx.x;
    const int tid = threadIdx.x;
    for (int idx = tid; idx < 4096; idx += 256) {
        int r = idx >> 10, k = idx & 1023;
        sw[r][k] = in[(2 * tp + r) * 1024 + k];
    }
    __syncthreads();
    const int ch = tid;
    float a0 = b[ch], a1 = b[ch];
    for (int dt = 0; dt < 3; ++dt)
        for (int k = 0; k < 1024; ++k) {
            float wv = w[(dt * 1024 + k) * 256 + ch];
            a0 = fmaf(wv, sw[dt][k], a0);
            a1 = fmaf(wv, sw[dt + 1][k], a1);
        }
    g_wpool1[tp * 256 + ch] = fmaxf(fmaxf(a0, 0.0f), fmaxf(a1, 0.0f));
}

// ============ wave conv2 k3 (256->256) + relu + pool2 ========================
__global__ void __launch_bounds__(256) k_wconv2(const float* __restrict__ w,
                                                const float* __restrict__ b) {
    __shared__ float sw[4][256];
    const int tp = blockIdx.x;
    const int tid = threadIdx.x;
    for (int idx = tid; idx < 1024; idx += 256) {
        int r = idx >> 8, k = idx & 255;
        sw[r][k] = g_wpool1[(2 * tp + r) * 256 + k];
    }
    __syncthreads();
    const int ch = tid;
    float a0 = b[ch], a1 = b[ch];
    for (int dt = 0; dt < 3; ++dt)
        for (int k = 0; k < 256; ++k) {
            float wv = w[(dt * 256 + k) * 256 + ch];
            a0 = fmaf(wv, sw[dt][k], a0);
            a1 = fmaf(wv, sw[dt + 1][k], a1);
        }
    g_wpool2[tp * 256 + ch] = fmaxf(fmaxf(a0, 0.0f), fmaxf(a1, 0.0f));
}

// ============ Xs[14,32256] @ s_Wi[32256,1024]: k-split partials ==============
__global__ void __launch_bounds__(256) k_sproj(const float* __restrict__ sWi) {
    __shared__ float xs[14 * 504];
    const int j = blockIdx.x * 256 + threadIdx.x;
    const int k0 = blockIdx.y * 504;
    for (int idx = threadIdx.x; idx < 14 * 504; idx += 256) {
        int t = idx / 504, kk = idx % 504;
        xs[idx] = g_pool2[t * 32256 + k0 + kk];
    }
    __syncthreads();
    float acc[14];
#pragma unroll
    for (int t = 0; t < 14; ++t) acc[t] = 0.f;
    for (int kk = 0; kk < 504; ++kk) {
        float wv = sWi[(size_t)(k0 + kk) * 1024 + j];
#pragma unroll
        for (int t = 0; t < 14; ++t) acc[t] = fmaf(xs[t * 504 + kk], wv, acc[t]);
    }
    for (int t = 0; t < 14; ++t)
        g_partial[(blockIdx.y * 14 + t) * 1024 + j] = acc[t];
}

__global__ void __launch_bounds__(256) k_sreduce(const float* __restrict__ sb) {
    const int idx = blockIdx.x * 256 + threadIdx.x;
    const int t = idx >> 10, j = idx & 1023;
    float a = sb[j];
    for (int kc = 0; kc < 64; ++kc) a += g_partial[(kc * 14 + t) * 1024 + j];
    g_xbs[t * 1024 + j] = a;
}

// ============ wave Wi projection =============================================
__global__ void __launch_bounds__(1024) k_wproj(const float* __restrict__ wWi,
                                                const float* __restrict__ wb) {
    __shared__ float yr[256];
    const int tid = threadIdx.x;
    if (tid < 256) yr[tid] = g_wpool2[blockIdx.x * 256 + tid];
    __syncthreads();
    float a = wb[tid];
    for (int k = 0; k < 256; ++k) a = fmaf(yr[k], wWi[k * 1024 + tid], a);
    g_xbw[blockIdx.x * 1024 + tid] = a;
}

// ============ small sequential LSTM (encoders) ===============================
__global__ void __launch_bounds__(1024) k_lstm_small(const float* __restrict__ Wh,
                                                     int mode) {
    __shared__ float h[256];
    __shared__ float zsm[1024];
    const int tid = threadIdx.x;
    const int T = mode ? 62 : 14;
    const float* xpre = mode ? g_xbw : g_xbs;
    float c = 0.0f;
    if (tid < 256) h[tid] = 0.0f;
    __syncthreads();
    for (int t = 0; t < T; ++t) {
        float acc = xpre[t * 1024 + tid];
#pragma unroll 8
        for (int k = 0; k < 256; ++k) acc = fmaf(h[k], Wh[k * 1024 + tid], acc);
        zsm[tid] = acc;
        __syncthreads();
        if (tid < 256) {
            float zi = zsm[tid], zf = zsm[256 + tid], zg = zsm[512 + tid], zo = zsm[768 + tid];
            c = sigm(zf) * c + sigm(zi) * tanhf(zg);
            h[tid] = sigm(zo) * tanhf(c);
        }
        __syncthreads();
    }
    if (tid < 256) {
        if (mode) { g_whh[tid] = h[tid]; g_wc[tid] = c; }
        else      { g_sh[tid]  = h[tid]; g_sc[tid] = c; }
    }
}

// ============ state reducers =================================================
__global__ void __launch_bounds__(256) k_reduce(const float* __restrict__ rhw,
                                                const float* __restrict__ rhb,
                                                const float* __restrict__ rcw,
                                                const float* __restrict__ rcb) {
    __shared__ float hcat[512], ccat[512];
    const int tid = threadIdx.x;
    hcat[tid] = g_sh[tid];  hcat[256 + tid] = g_whh[tid];
    ccat[tid] = g_sc[tid];  ccat[256 + tid] = g_wc[tid];
    __syncthreads();
    float ah = rhb[tid], ac = rcb[tid];
    for (int k = 0; k < 512; ++k) {
        ah = fmaf(hcat[k], rhw[k * 256 + tid], ah);
        ac = fmaf(ccat[k], rcw[k * 256 + tid], ac);
    }
    g_h0[tid] = ah;
    g_c0[tid] = ac;
}

// ============ decoder prep ===================================================
__global__ void __launch_bounds__(1024) k_dprep(const float* __restrict__ emb,
                                                const float* __restrict__ dWi,
                                                const float* __restrict__ db) {
    __shared__ float er[256];
    const int tid = threadIdx.x;
    if (tid < 256) er[tid] = emb[blockIdx.x * 256 + tid];
    __syncthreads();
    float a = db[tid];
    for (int d = 0; d < 256; ++d) a = fmaf(er[d], dWi[d * 1024 + tid], a);
    int gate = tid >> 8, cg = tid & 255, r = cg >> 5, u = cg & 31;
    g_xiR[blockIdx.x * 1024 + r * 128 + gate * 32 + u] = a;
}

__global__ void __launch_bounds__(1024) k_whprep(const float* __restrict__ dWh) {
    const int k = blockIdx.x, j = threadIdx.x;
    int gate = j >> 8, cg = j & 255, r = cg >> 5, u = cg & 31;
    g_WhR[r * 32768 + k * 128 + gate * 32 + u] = dWh[k * 1024 + j];
}

__global__ void __launch_bounds__(256) k_tokprep(const float* __restrict__ dec) {
    const int w = blockIdx.x * 256 + threadIdx.x;
    if (w >= 1196) return;
    unsigned int bits = 0;
    for (int i = 0; i < 32; ++i)
        if (dec[w * 32 + i] > 0.5f) bits |= (1u << i);
    g_tokbits[w] = bits;
}

// ============ persistent decoder: 8-CTA cluster, register-resident weights ===
__global__ void __cluster_dims__(8, 1, 1) __launch_bounds__(256, 1)
k_decoder() {
    __shared__ float hb[2][256];
    __shared__ float xis[2][128];
    __shared__ float zs[256];
    __shared__ unsigned int tokw[1196];
    __shared__ __align__(8) unsigned long long mbar[4];

    const int r = blockIdx.x;
    const int t = threadIdx.x;
    const int jl = t & 127;
    const int half = t >> 7;

    // register-resident weight slice: w[i] = WhR[r][half*128+i][jl]
    float w[128];
    {
        const float* Wg = g_WhR + r * 32768 + (half * 128) * 128 + jl;
#pragma unroll
        for (int i = 0; i < 128; ++i) w[i] = Wg[i * 128];
    }
    if (t < 128) {
        xis[0][t] = g_xiR[r * 128 + t];
        xis[1][t] = g_xiR[1024 + r * 128 + t];
    }
    hb[0][t] = g_h0[t];
    for (int idx = t; idx < 1196; idx += 256) tokw[idx] = g_tokbits[idx];
    float c = (t < 32) ? g_c0[r * 32 + t] : 0.0f;

    const uint32_t mbar_addr = (uint32_t)__cvta_generic_to_shared(&mbar[0]);
    const uint32_t hb_addr = (uint32_t)__cvta_generic_to_shared(&hb[0][0]);
    if (t == 0) {
#pragma unroll
        for (int i = 0; i < 4; ++i) mbar_init(mbar_addr + 8u * i, 8);
    }
    __syncthreads();
    asm volatile("barrier.cluster.arrive.aligned;" ::: "memory");
    asm volatile("barrier.cluster.wait.aligned;" ::: "memory");

    uint32_t peer_hb[8], peer_mb[8];
    if (t < 32) {
#pragma unroll
        for (int rr = 0; rr < 8; ++rr) {
            peer_hb[rr] = mapa_u32(hb_addr, rr);
            peer_mb[rr] = mapa_u32(mbar_addr, rr);
        }
    }

    for (int s = 0; s < 38272; ++s) {
        if (s) mbar_wait(mbar_addr + 8u * ((s - 1) & 3), (uint32_t)(((s - 1) >> 2) & 1));
        const float4* h4 = (const float4*)(&hb[s & 1][half * 128]);
        float a[8];
#pragma unroll
        for (int j = 0; j < 8; ++j) a[j] = 0.0f;
#pragma unroll
        for (int q = 0; q < 32; ++q) {
            float4 hv = h4[q];
            a[(4 * q + 0) & 7] = fmaf(hv.x, w[4 * q + 0], a[(4 * q + 0) & 7]);
            a[(4 * q + 1) & 7] = fmaf(hv.y, w[4 * q + 1], a[(4 * q + 1) & 7]);
            a[(4 * q + 2) & 7] = fmaf(hv.z, w[4 * q + 2], a[(4 * q + 2) & 7]);
            a[(4 * q + 3) & 7] = fmaf(hv.w, w[4 * q + 3], a[(4 * q + 3) & 7]);
        }
        float zv = ((a[0] + a[1]) + (a[2] + a[3])) + ((a[4] + a[5]) + (a[6] + a[7]));
        if (half == 0) {
            const int tok = (tokw[s >> 5] >> (s & 31)) & 1;
            zv += xis[tok][jl];
        }
        zs[half * 128 + jl] = zv;
        __syncthreads();
        if (t < 32) {
            const int u = t;
            float zi = zs[u]      + zs[128 + u];
            float zf = zs[32 + u] + zs[160 + u];
            float zg = zs[64 + u] + zs[192 + u];
            float zo = zs[96 + u] + zs[224 + u];
            c = fsigm(zf) * c + fsigm(zi) * ftanh(zg);
            float hn = fsigm(zo) * ftanh(c);
            const uint32_t boff = (uint32_t)((256 * ((s + 1) & 1) + r * 32 + u) * 4);
#pragma unroll
            for (int rr = 0; rr < 8; ++rr) st_remote_f32(peer_hb[rr] + boff, hn);
            __syncwarp();
            if (t == 0) {
                const uint32_t moff = 8u * (uint32_t)(s & 3);
#pragma unroll
                for (int rr = 0; rr < 8; ++rr) mbar_arrive_remote(peer_mb[rr] + moff);
            }
            g_hs[(size_t)s * 256 + r * 32 + u] = hn;
        }
    }
}

// ============ epilogue: softmax(hs @ out_w + out_b), 16 steps/block ==========
__global__ void __launch_bounds__(128) k_softmax(const float* __restrict__ ow,
                                                 const float* __restrict__ ob,
                                                 float* __restrict__ out) {
    __shared__ float hsr[16 * 256];
    __shared__ float red[128];
    const int s0 = blockIdx.x * 16;
    const int w = threadIdx.x;
    for (int idx = w; idx < 4096; idx += 128) hsr[idx] = g_hs[(size_t)s0 * 256 + idx];
    __syncthreads();
    float a[16];
    const float bb = ob[w];
#pragma unroll
    for (int i = 0; i < 16; ++i) a[i] = bb;
    for (int d = 0; d < 256; ++d) {
        float wv = ow[d * 128 + w];
#pragma unroll
        for (int i = 0; i < 16; ++i) a[i] = fmaf(hsr[i * 256 + d], wv, a[i]);
    }
#pragma unroll 1
    for (int i = 0; i < 16; ++i) {
        red[w] = a[i];
        __syncthreads();
        for (int off = 64; off; off >>= 1) {
            if (w < off) red[w] = fmaxf(red[w], red[w + off]);
            __syncthreads();
        }
        float m = red[0];
        __syncthreads();
        float e = __expf(a[i] - m);
        red[w] = e;
        __syncthreads();
        for (int off = 64; off; off >>= 1) {
            if (w < off) red[w] += red[w + off];
            __syncthreads();
        }
        float ssum = red[0];
        __syncthreads();
        int s = s0 + i, tt = s >> 7, v = s & 127;
        out[((size_t)v * 300 + tt) * 128 + w] = e / ssum;
    }
}

// ============ zero the unwritten last time slot out[:,299,:] =================
__global__ void __launch_bounds__(256) k_zero(float* __restrict__ out) {
    const int idx = blockIdx.x * 256 + threadIdx.x;
    const int v = idx >> 7, w = idx & 127;
    out[((size_t)v * 300 + 299) * 128 + w] = 0.0f;
}

// ============================================================================
extern "C" void kernel_launch(void* const* d_in, const int* in_sizes, int n_in,
                              void* d_out, int out_size) {
    const float* stft = (const float*)d_in[0];
    const float* wave = (const float*)d_in[1];
    const float* dec  = (const float*)d_in[2];
    const float* scw1 = (const float*)d_in[3];
    const float* scb1 = (const float*)d_in[4];
    const float* scw2 = (const float*)d_in[5];
    const float* scb2 = (const float*)d_in[6];
    const float* sWi  = (const float*)d_in[7];
    const float* sWh  = (const float*)d_in[8];
    const float* sb   = (const float*)d_in[9];
    const float* wcw1 = (const float*)d_in[10];
    const float* wcb1 = (const float*)d_in[11];
    const float* wcw2 = (const float*)d_in[12];
    const float* wcb2 = (const float*)d_in[13];
    const float* wWi  = (const float*)d_in[14];
    const float* wWh  = (const float*)d_in[15];
    const float* wb   = (const float*)d_in[16];
    const float* rhw  = (const float*)d_in[17];
    const float* rhb  = (const float*)d_in[18];
    const float* rcw  = (const float*)d_in[19];
    const float* rcb  = (const float*)d_in[20];
    const float* emb  = (const float*)d_in[21];
    const float* dWi  = (const float*)d_in[22];
    const float* dWh  = (const float*)d_in[23];
    const float* db   = (const float*)d_in[24];
    const float* ow   = (const float*)d_in[25];
    const float* ob   = (const float*)d_in[26];
    float* out = (float*)d_out;
    (void)in_sizes; (void)n_in; (void)out_size;

    // ---- STFT encoder ----
    k_sconv1<<<31 * 255, 256>>>(stft, scw1, scb1);
    k_sconv2<<<dim3(42, 14), 256>>>(scw2, scb2);
    k_sproj<<<dim3(4, 64), 256>>>(sWi);
    k_sreduce<<<56, 256>>>(sb);
    k_lstm_small<<<1, 1024>>>(sWh, 0);

    // ---- waveform encoder ----
    k_wconv1<<<127, 256>>>(wave, wcw1, wcb1);
    k_wconv2<<<62, 256>>>(wcw2, wcb2);
    k_wproj<<<62, 1024>>>(wWi, wb);
    k_lstm_small<<<1, 1024>>>(wWh, 1);

    // ---- reducers + decoder prep ----
    k_reduce<<<1, 256>>>(rhw, rhb, rcw, rcb);
    k_dprep<<<2, 1024>>>(emb, dWi, db);
    k_whprep<<<256, 1024>>>(dWh);
    k_tokprep<<<5, 256>>>(dec);

    // ---- sequential decoder (8-CTA cluster, reg-resident W, light handshake) ----
    k_decoder<<<8, 256>>>();

    // ---- parallel softmax epilogue + zero last slot ----
    k_softmax<<<2392, 128>>>(ow, ob, out);
    k_zero<<<64, 256>>>(out);
}

// round 15
// speedup vs baseline: 4.1111x; 3.4425x over previous
#include <cuda_runtime.h>
#include <cuda_bf16.h>
#include <cstdint>
#include <math.h>

#define DINL __device__ __forceinline__
DINL float sigm(float x) { return 1.0f / (1.0f + expf(-x)); }  // accurate (encoders)
DINL float ftanh(float x) { float y; asm("tanh.approx.f32 %0, %1;" : "=f"(y) : "f"(x)); return y; }
DINL float fsigm(float x) { return fmaf(ftanh(0.5f * x), 0.5f, 0.5f); }  // fast (decoder)

DINL uint32_t mapa_u32(uint32_t addr, int rank) {
    uint32_t r;
    asm("mapa.shared::cluster.u32 %0, %1, %2;" : "=r"(r) : "r"(addr), "r"(rank));
    return r;
}
DINL void mbar_init(uint32_t addr, uint32_t cnt) {
    asm volatile("mbarrier.init.shared.b64 [%0], %1;" :: "r"(addr), "r"(cnt) : "memory");
}
DINL void mbar_expect(uint32_t addr, uint32_t tx) {
    asm volatile("mbarrier.arrive.expect_tx.shared.b64 _, [%0], %1;"
                 :: "r"(addr), "r"(tx) : "memory");
}
DINL void mbar_wait(uint32_t addr, uint32_t parity) {
    asm volatile(
        "{\n\t"
        ".reg .pred P;\n\t"
        "LAB_%=:\n\t"
        "mbarrier.try_wait.parity.acquire.cluster.shared::cta.b64 P, [%0], %1, 0x989680;\n\t"
        "@!P bra LAB_%=;\n\t"
        "}\n"
        :: "r"(addr), "r"(parity) : "memory");
}
// fused remote store + remote mbarrier complete_tx (8 bytes per op)
DINL void st_async64(uint32_t dst, unsigned long long v, uint32_t mb) {
    asm volatile("st.async.shared::cluster.mbarrier::complete_tx::bytes.b64 [%0], %1, [%2];"
                 :: "r"(dst), "l"(v), "r"(mb) : "memory");
}
DINL unsigned long long fma2(unsigned long long a, unsigned long long b, unsigned long long c) {
    unsigned long long d;
    asm("fma.rn.f32x2 %0, %1, %2, %3;" : "=l"(d) : "l"(a), "l"(b), "l"(c));
    return d;
}
DINL float lo32(unsigned long long v) { return __uint_as_float((unsigned)v); }
DINL float hi32(unsigned long long v) { return __uint_as_float((unsigned)(v >> 32)); }

// ---------------- scratch (__device__ globals, no allocation) ---------------
__device__ float g_pool1[31 * 255 * 256];
__device__ float g_pool2[14 * 126 * 256];
__device__ float g_partial[64 * 14 * 1024];
__device__ float g_xbs[14 * 1024];
__device__ float g_wpool1[127 * 256];
__device__ float g_wpool2[62 * 256];
__device__ float g_xbw[62 * 1024];
__device__ float g_sh[256], g_sc[256], g_whh[256], g_wc[256];
__device__ float g_h0[256], g_c0[256];
__device__ float g_xiR[2 * 1024];
__device__ unsigned long long g_WhR2[8 * 128 * 128];  // packed f32x2 weight pairs
__device__ unsigned int g_tokbits[1196];
__device__ float g_hs[38272 * 256];

// ============ STFT conv1 3x3 (1->256) + relu + maxpool 2x2 ===================
__global__ void __launch_bounds__(256) k_sconv1(const float* __restrict__ in,
                                                const float* __restrict__ w,
                                                const float* __restrict__ b) {
    const int blk = blockIdx.x;
    const int tp = blk / 255, fp = blk % 255;
    __shared__ float patch[4][4];
    const int tid = threadIdx.x;
    if (tid < 16) {
        int rr = tid >> 2, cc = tid & 3;
        patch[rr][cc] = in[(2 * tp + rr) * 513 + (2 * fp + cc)];
    }
    __syncthreads();
    const int ch = tid;
    float wr[9];
#pragma unroll
    for (int t = 0; t < 9; ++t) wr[t] = w[t * 256 + ch];
    const float bb = b[ch];
    float best = -1e30f;
#pragma unroll
    for (int a = 0; a < 2; ++a)
#pragma unroll
        for (int bc = 0; bc < 2; ++bc) {
            float acc = bb;
#pragma unroll
            for (int i = 0; i < 3; ++i)
#pragma unroll
                for (int j = 0; j < 3; ++j)
                    acc = fmaf(patch[a + i][bc + j], wr[i * 3 + j], acc);
            best = fmaxf(best, fmaxf(acc, 0.0f));
        }
    g_pool1[(tp * 255 + fp) * 256 + ch] = best;
}

// ============ STFT conv2 3x3 (256->256) + relu + maxpool 2x2 =================
__global__ void __launch_bounds__(256) k_sconv2(const float* __restrict__ w2,
                                                const float* __restrict__ b2) {
    __shared__ float sin_[4 * 8 * 256];
    const int tp = blockIdx.y;
    const int fp0 = blockIdx.x * 3;
    const int tid = threadIdx.x;
    for (int idx = tid; idx < 4 * 8 * 256; idx += 256) {
        int ch = idx & 255;
        int col = (idx >> 8) & 7;
        int row = idx >> 11;
        sin_[idx] = g_pool1[((2 * tp + row) * 255 + (2 * fp0 + col)) * 256 + ch];
    }
    __syncthreads();
    const int ch = tid;
    float a[2][6];
    const float bb = b2[ch];
#pragma unroll
    for (int r2 = 0; r2 < 2; ++r2)
#pragma unroll
        for (int cc = 0; cc < 6; ++cc) a[r2][cc] = bb;
    for (int ic = 0; ic < 256; ++ic) {
        float rv[4][8];
#pragma unroll
        for (int rr = 0; rr < 4; ++rr)
#pragma unroll
            for (int cc = 0; cc < 8; ++cc) rv[rr][cc] = sin_[(rr * 8 + cc) * 256 + ic];
#pragma unroll
        for (int i = 0; i < 3; ++i)
#pragma unroll
            for (int j = 0; j < 3; ++j) {
                float wv = w2[((i * 3 + j) * 256 + ic) * 256 + ch];
#pragma unroll
                for (int r2 = 0; r2 < 2; ++r2)
#pragma unroll
                    for (int cc = 0; cc < 6; ++cc)
                        a[r2][cc] = fmaf(wv, rv[r2 + i][cc + j], a[r2][cc]);
            }
    }
#pragma unroll
    for (int cc2 = 0; cc2 < 3; ++cc2) {
        float m = -1e30f;
#pragma unroll
        for (int r2 = 0; r2 < 2; ++r2)
#pragma unroll
            for (int q = 0; q < 2; ++q)
                m = fmaxf(m, fmaxf(a[r2][2 * cc2 + q], 0.0f));
        g_pool2[(tp * 126 + (fp0 + cc2)) * 256 + ch] = m;
    }
}

// ============ wave conv1 k3 (1024->256) + relu + pool2 =======================
__global__ void __launch_bounds__(256) k_wconv1(const float* __restrict__ in,
                                                const float* __restrict__ w,
                                                const float* __restrict__ b) {
    __shared__ float sw[4][1024];
    const int tp = blockIdx.x;
    const int tid = threadIdx.x;
    for (int idx = tid; idx < 4096; idx += 256) {
        int r = idx >> 10, k = idx & 1023;
        sw[r][k] = in[(2 * tp + r) * 1024 + k];
    }
    __syncthreads();
    const int ch = tid;
    float a0 = b[ch], a1 = b[ch];
    for (int dt = 0; dt < 3; ++dt)
        for (int k = 0; k < 1024; ++k) {
            float wv = w[(dt * 1024 + k) * 256 + ch];
            a0 = fmaf(wv, sw[dt][k], a0);
            a1 = fmaf(wv, sw[dt + 1][k], a1);
        }
    g_wpool1[tp * 256 + ch] = fmaxf(fmaxf(a0, 0.0f), fmaxf(a1, 0.0f));
}

// ============ wave conv2 k3 (256->256) + relu + pool2 ========================
__global__ void __launch_bounds__(256) k_wconv2(const float* __restrict__ w,
                                                const float* __restrict__ b) {
    __shared__ float sw[4][256];
    const int tp = blockIdx.x;
    const int tid = threadIdx.x;
    for (int idx = tid; idx < 1024; idx += 256) {
        int r = idx >> 8, k = idx & 255;
        sw[r][k] = g_wpool1[(2 * tp + r) * 256 + k];
    }
    __syncthreads();
    const int ch = tid;
    float a0 = b[ch], a1 = b[ch];
    for (int dt = 0; dt < 3; ++dt)
        for (int k = 0; k < 256; ++k) {
            float wv = w[(dt * 256 + k) * 256 + ch];
            a0 = fmaf(wv, sw[dt][k], a0);
            a1 = fmaf(wv, sw[dt + 1][k], a1);
        }
    g_wpool2[tp * 256 + ch] = fmaxf(fmaxf(a0, 0.0f), fmaxf(a1, 0.0f));
}

// ============ Xs[14,32256] @ s_Wi[32256,1024]: k-split partials ==============
__global__ void __launch_bounds__(256) k_sproj(const float* __restrict__ sWi) {
    __shared__ float xs[14 * 504];
    const int j = blockIdx.x * 256 + threadIdx.x;
    const int k0 = blockIdx.y * 504;
    for (int idx = threadIdx.x; idx < 14 * 504; idx += 256) {
        int t = idx / 504, kk = idx % 504;
        xs[idx] = g_pool2[t * 32256 + k0 + kk];
    }
    __syncthreads();
    float acc[14];
#pragma unroll
    for (int t = 0; t < 14; ++t) acc[t] = 0.f;
    for (int kk = 0; kk < 504; ++kk) {
        float wv = sWi[(size_t)(k0 + kk) * 1024 + j];
#pragma unroll
        for (int t = 0; t < 14; ++t) acc[t] = fmaf(xs[t * 504 + kk], wv, acc[t]);
    }
    for (int t = 0; t < 14; ++t)
        g_partial[(blockIdx.y * 14 + t) * 1024 + j] = acc[t];
}

__global__ void __launch_bounds__(256) k_sreduce(const float* __restrict__ sb) {
    const int idx = blockIdx.x * 256 + threadIdx.x;
    const int t = idx >> 10, j = idx & 1023;
    float a = sb[j];
    for (int kc = 0; kc < 64; ++kc) a += g_partial[(kc * 14 + t) * 1024 + j];
    g_xbs[t * 1024 + j] = a;
}

// ============ wave Wi projection =============================================
__global__ void __launch_bounds__(1024) k_wproj(const float* __restrict__ wWi,
                                                const float* __restrict__ wb) {
    __shared__ float yr[256];
    const int tid = threadIdx.x;
    if (tid < 256) yr[tid] = g_wpool2[blockIdx.x * 256 + tid];
    __syncthreads();
    float a = wb[tid];
    for (int k = 0; k < 256; ++k) a = fmaf(yr[k], wWi[k * 1024 + tid], a);
    g_xbw[blockIdx.x * 1024 + tid] = a;
}

// ============ small sequential LSTM (encoders) ===============================
__global__ void __launch_bounds__(1024) k_lstm_small(const float* __restrict__ Wh,
                                                     int mode) {
    __shared__ float h[256];
    __shared__ float zsm[1024];
    const int tid = threadIdx.x;
    const int T = mode ? 62 : 14;
    const float* xpre = mode ? g_xbw : g_xbs;
    float c = 0.0f;
    if (tid < 256) h[tid] = 0.0f;
    __syncthreads();
    for (int t = 0; t < T; ++t) {
        float acc = xpre[t * 1024 + tid];
#pragma unroll 8
        for (int k = 0; k < 256; ++k) acc = fmaf(h[k], Wh[k * 1024 + tid], acc);
        zsm[tid] = acc;
        __syncthreads();
        if (tid < 256) {
            float zi = zsm[tid], zf = zsm[256 + tid], zg = zsm[512 + tid], zo = zsm[768 + tid];
            c = sigm(zf) * c + sigm(zi) * tanhf(zg);
            h[tid] = sigm(zo) * tanhf(c);
        }
        __syncthreads();
    }
    if (tid < 256) {
        if (mode) { g_whh[tid] = h[tid]; g_wc[tid] = c; }
        else      { g_sh[tid]  = h[tid]; g_sc[tid] = c; }
    }
}

// ============ state reducers =================================================
__global__ void __launch_bounds__(256) k_reduce(const float* __restrict__ rhw,
                                                const float* __restrict__ rhb,
                                                const float* __restrict__ rcw,
                                                const float* __restrict__ rcb) {
    __shared__ float hcat[512], ccat[512];
    const int tid = threadIdx.x;
    hcat[tid] = g_sh[tid];  hcat[256 + tid] = g_whh[tid];
    ccat[tid] = g_sc[tid];  ccat[256 + tid] = g_wc[tid];
    __syncthreads();
    float ah = rhb[tid], ac = rcb[tid];
    for (int k = 0; k < 512; ++k) {
        ah = fmaf(hcat[k], rhw[k * 256 + tid], ah);
        ac = fmaf(ccat[k], rcw[k * 256 + tid], ac);
    }
    g_h0[tid] = ah;
    g_c0[tid] = ac;
}

// ============ decoder prep ===================================================
__global__ void __launch_bounds__(1024) k_dprep(const float* __restrict__ emb,
                                                const float* __restrict__ dWi,
                                                const float* __restrict__ db) {
    __shared__ float er[256];
    const int tid = threadIdx.x;
    if (tid < 256) er[tid] = emb[blockIdx.x * 256 + tid];
    __syncthreads();
    float a = db[tid];
    for (int d = 0; d < 256; ++d) a = fmaf(er[d], dWi[d * 1024 + tid], a);
    int gate = tid >> 8, cg = tid & 255, r = cg >> 5, u = cg & 31;
    g_xiR[blockIdx.x * 1024 + r * 128 + gate * 32 + u] = a;
}

// pack d_Wh into per-rank f32x2 pairs: pair q holds (W[2q][j], W[2q+1][j])
__global__ void __launch_bounds__(1024) k_whprep2(const float* __restrict__ dWh) {
    const int k = blockIdx.x;     // 0..255
    const int j = threadIdx.x;    // 0..1023
    int gate = j >> 8, cg = j & 255, rr = cg >> 5, u = cg & 31;
    int jl = gate * 32 + u;
    float* f = (float*)g_WhR2;
    f[((((size_t)rr * 128 + (k >> 1)) * 128 + jl) << 1) | (k & 1)] = dWh[k * 1024 + j];
}

__global__ void __launch_bounds__(256) k_tokprep(const float* __restrict__ dec) {
    const int w = blockIdx.x * 256 + threadIdx.x;
    if (w >= 1196) return;
    unsigned int bits = 0;
    for (int i = 0; i < 32; ++i)
        if (dec[w * 32 + i] > 0.5f) bits |= (1u << i);
    g_tokbits[w] = bits;
}

// ============ persistent decoder: 8-CTA cluster, st.async handshake ==========
__global__ void __cluster_dims__(8, 1, 1) __launch_bounds__(256, 1)
k_decoder() {
    __shared__ float hb[2][256];
    __shared__ float xis[2][128];
    __shared__ float zs[256];
    __shared__ unsigned int tokw[1196];
    __shared__ __align__(8) unsigned long long mbar[4];

    const int r = blockIdx.x;
    const int t = threadIdx.x;
    const int jl = t & 127;
    const int half = t >> 7;

    // register-resident packed weight pairs
    unsigned long long w2[64];
    {
        const unsigned long long* G = g_WhR2 + ((size_t)(r * 128 + half * 64)) * 128 + jl;
#pragma unroll
        for (int i = 0; i < 64; ++i) w2[i] = G[i * 128];
    }
    if (t < 128) {
        xis[0][t] = g_xiR[r * 128 + t];
        xis[1][t] = g_xiR[1024 + r * 128 + t];
    }
    hb[0][t] = g_h0[t];
    for (int idx = t; idx < 1196; idx += 256) tokw[idx] = g_tokbits[idx];
    float c = (t < 32) ? g_c0[r * 32 + t] : 0.0f;

    const uint32_t mbar_addr = (uint32_t)__cvta_generic_to_shared(&mbar[0]);
    const uint32_t hb_addr = (uint32_t)__cvta_generic_to_shared(&hb[0][0]);
    if (t == 0) {
#pragma unroll
        for (int i = 0; i < 4; ++i) mbar_init(mbar_addr + 8u * i, 1);
        mbar_expect(mbar_addr, 1024);   // prime slot 0 (step-0 sends)
    }
    __syncthreads();
    asm volatile("barrier.cluster.arrive.aligned;" ::: "memory");
    asm volatile("barrier.cluster.wait.aligned;" ::: "memory");

    uint32_t peer_hb[8], peer_mb[8];
#pragma unroll
    for (int rr = 0; rr < 8; ++rr) {
        peer_hb[rr] = mapa_u32(hb_addr, rr);
        peer_mb[rr] = mapa_u32(mbar_addr, rr);
    }

    for (int s = 0; s < 38272; ++s) {
        if (s) mbar_wait(mbar_addr + 8u * ((s - 1) & 3), (uint32_t)(((s - 1) >> 2) & 1));

        const double2* h2 = (const double2*)(&hb[s & 1][half * 128]);
        unsigned long long a0 = 0, a1 = 0, a2 = 0, a3 = 0;
#pragma unroll
        for (int q = 0; q < 32; ++q) {
            double2 hv = h2[q];
            unsigned long long hx = __double_as_longlong(hv.x);
            unsigned long long hy = __double_as_longlong(hv.y);
            if (q & 1) {
                a2 = fma2(w2[2 * q], hx, a2);
                a3 = fma2(w2[2 * q + 1], hy, a3);
            } else {
                a0 = fma2(w2[2 * q], hx, a0);
                a1 = fma2(w2[2 * q + 1], hy, a1);
            }
        }
        float zv = ((lo32(a0) + hi32(a0)) + (lo32(a1) + hi32(a1))) +
                   ((lo32(a2) + hi32(a2)) + (lo32(a3) + hi32(a3)));
        if (half == 0) {
            const int tok = (tokw[s >> 5] >> (s & 31)) & 1;
            zv += xis[tok][jl];
        }
        zs[t] = zv;
        __syncthreads();
        if (t < 32) {
            const int u = t;
            float zi = zs[u]      + zs[128 + u];
            float zf = zs[32 + u] + zs[160 + u];
            float zg = zs[64 + u] + zs[192 + u];
            float zo = zs[96 + u] + zs[224 + u];
            c = fsigm(zf) * c + fsigm(zi) * ftanh(zg);
            float hn = fsigm(zo) * ftanh(c);
            g_hs[(size_t)s * 256 + r * 32 + u] = hn;
            float hnp = __shfl_down_sync(0xffffffffu, hn, 1);
            if (t == 0 && s + 1 < 38272)
                mbar_expect(mbar_addr + 8u * ((s + 1) & 3), 1024);  // expect for step s+1
            __syncwarp();
            if (s < 38271 && !(u & 1)) {
                unsigned long long val =
                    (unsigned long long)__float_as_uint(hn) |
                    ((unsigned long long)__float_as_uint(hnp) << 32);
                const uint32_t boff = (uint32_t)((256 * ((s + 1) & 1) + r * 32 + u) * 4);
                const uint32_t moff = 8u * (uint32_t)(s & 3);
#pragma unroll
                for (int rr = 0; rr < 8; ++rr)
                    st_async64(peer_hb[rr] + boff, val, peer_mb[rr] + moff);
            }
        }
    }
    asm volatile("barrier.cluster.arrive.aligned;" ::: "memory");
    asm volatile("barrier.cluster.wait.aligned;" ::: "memory");
}

// ============ epilogue: softmax(hs @ out_w + out_b), 16 steps/block ==========
__global__ void __launch_bounds__(128) k_softmax(const float* __restrict__ ow,
                                                 const float* __restrict__ ob,
                                                 float* __restrict__ out) {
    __shared__ float hsr[16 * 256];
    __shared__ float red[128];
    const int s0 = blockIdx.x * 16;
    const int w = threadIdx.x;
    for (int idx = w; idx < 4096; idx += 128) hsr[idx] = g_hs[(size_t)s0 * 256 + idx];
    __syncthreads();
    float a[16];
    const float bb = ob[w];
#pragma unroll
    for (int i = 0; i < 16; ++i) a[i] = bb;
    for (int d = 0; d < 256; ++d) {
        float wv = ow[d * 128 + w];
#pragma unroll
        for (int i = 0; i < 16; ++i) a[i] = fmaf(hsr[i * 256 + d], wv, a[i]);
    }
#pragma unroll 1
    for (int i = 0; i < 16; ++i) {
        red[w] = a[i];
        __syncthreads();
        for (int off = 64; off; off >>= 1) {
            if (w < off) red[w] = fmaxf(red[w], red[w + off]);
            __syncthreads();
        }
        float m = red[0];
        __syncthreads();
        float e = __expf(a[i] - m);
        red[w] = e;
        __syncthreads();
        for (int off = 64; off; off >>= 1) {
            if (w < off) red[w] += red[w + off];
            __syncthreads();
        }
        float ssum = red[0];
        __syncthreads();
        int s = s0 + i, tt = s >> 7, v = s & 127;
        out[((size_t)v * 300 + tt) * 128 + w] = e / ssum;
    }
}

// ============ zero the unwritten last time slot out[:,299,:] =================
__global__ void __launch_bounds__(256) k_zero(float* __restrict__ out) {
    const int idx = blockIdx.x * 256 + threadIdx.x;
    const int v = idx >> 7, w = idx & 127;
    out[((size_t)v * 300 + 299) * 128 + w] = 0.0f;
}

// ============================================================================
extern "C" void kernel_launch(void* const* d_in, const int* in_sizes, int n_in,
                              void* d_out, int out_size) {
    const float* stft = (const float*)d_in[0];
    const float* wave = (const float*)d_in[1];
    const float* dec  = (const float*)d_in[2];
    const float* scw1 = (const float*)d_in[3];
    const float* scb1 = (const float*)d_in[4];
    const float* scw2 = (const float*)d_in[5];
    const float* scb2 = (const float*)d_in[6];
    const float* sWi  = (const float*)d_in[7];
    const float* sWh  = (const float*)d_in[8];
    const float* sb   = (const float*)d_in[9];
    const float* wcw1 = (const float*)d_in[10];
    const float* wcb1 = (const float*)d_in[11];
    const float* wcw2 = (const float*)d_in[12];
    const float* wcb2 = (const float*)d_in[13];
    const float* wWi  = (const float*)d_in[14];
    const float* wWh  = (const float*)d_in[15];
    const float* wb   = (const float*)d_in[16];
    const float* rhw  = (const float*)d_in[17];
    const float* rhb  = (const float*)d_in[18];
    const float* rcw  = (const float*)d_in[19];
    const float* rcb  = (const float*)d_in[20];
    const float* emb  = (const float*)d_in[21];
    const float* dWi  = (const float*)d_in[22];
    const float* dWh  = (const float*)d_in[23];
    const float* db   = (const float*)d_in[24];
    const float* ow   = (const float*)d_in[25];
    const float* ob   = (const float*)d_in[26];
    float* out = (float*)d_out;
    (void)in_sizes; (void)n_in; (void)out_size;

    // ---- STFT encoder ----
    k_sconv1<<<31 * 255, 256>>>(stft, scw1, scb1);
    k_sconv2<<<dim3(42, 14), 256>>>(scw2, scb2);
    k_sproj<<<dim3(4, 64), 256>>>(sWi);
    k_sreduce<<<56, 256>>>(sb);
    k_lstm_small<<<1, 1024>>>(sWh, 0);

    // ---- waveform encoder ----
    k_wconv1<<<127, 256>>>(wave, wcw1, wcb1);
    k_wconv2<<<62, 256>>>(wcw2, wcb2);
    k_wproj<<<62, 1024>>>(wWi, wb);
    k_lstm_small<<<1, 1024>>>(wWh, 1);

    // ---- reducers + decoder prep ----
    k_reduce<<<1, 256>>>(rhw, rhb, rcw, rcb);
    k_dprep<<<2, 1024>>>(emb, dWi, db);
    k_whprep2<<<256, 1024>>>(dWh);
    k_tokprep<<<5, 256>>>(dec);

    // ---- sequential decoder (8-CTA cluster, f32x2 + st.async handshake) ----
    k_decoder<<<8, 256>>>();

    // ---- parallel softmax epilogue + zero last slot ----
    k_softmax<<<2392, 128>>>(ow, ob, out);
    k_zero<<<64, 256>>>(out);
}